// round 12
// baseline (speedup 1.0000x reference)
#include <cuda_runtime.h>
#include <cuda_fp16.h>
#include <cstdint>

#define DD   256
#define KK   8192
#define NN   32768
#define CTAM 128
#define NSPLIT 16                 // rescue N-splits (512 codes each)

// ---- pass1 smem layout (A = a0 only, 4 planes; CTAN=128; 2-stage 16KB B ring)
#define P1_CTAN   128
#define P1_OFF_A  0               // 4 x 16384 = 65536
#define P1_OFF_B  65536           // 2 stages x 16384 = 32768  (+ spare stage slot)
#define P1_OFF_HN 114688          // 128 floats
#define P1_SMEM   115200
#define P1_OFF_RV P1_OFF_B
#define P1_OFF_RI (P1_OFF_B + 2048)
#define P1_OFF_R2 (P1_OFF_B + 4096)

// ---- rescue smem layout (A = [a0|a1], 8 planes; 3-stage 32KB ring; CTAN=256)
#define CTAN 256
#define RS_OFF_A  0               // 8 x 16384 = 131072
#define RS_OFF_B  131072          // 3 stages x 32768
#define RS_OFF_HN 229376
#define RS_SMEM   230400
#define RS_OFF_RV RS_OFF_B
#define RS_OFF_RI (RS_OFF_B + 2048)

#define SWZ(x) ((x) ^ (((x) >> 3) & 0x70))

// Scratch (no allocations allowed)
__device__ float d_half_norm[KK];
__device__ float d_a0norm[NN];
__device__ float d_rxnorm[NN];
__device__ int   d_usage[KK];
__device__ int   d_indices[NN];
__device__ int   d_count;
__device__ int   d_b0max_bits;    // monotonic across replays (same inputs) - no reset needed
__device__ int   d_remax_bits;
__device__ int   d_amb[NN];
__device__ float d_resc_v[NSPLIT * NN];
__device__ int   d_resc_i[NSPLIT * NN];
__device__ __half d_A[(size_t)NN * 512];   // [a0(256) | a1(256)] per row (for rescue)
__device__ __half d_B[(size_t)KK * 512];   // [b0(256) | b1(256)] per row

__device__ __forceinline__ uint32_t smem_u32(const void* p) {
    uint32_t a;
    asm("{ .reg .u64 t; cvta.to.shared.u64 t, %1; cvt.u32.u64 %0, t; }" : "=r"(a) : "l"(p));
    return a;
}

// ---------------------------------------------------------------------------
// Codebook split: exact 2-way fp16 split + exact split-part norms (warp/row).
// Also resets d_count (before pass1) and d_usage.
// ---------------------------------------------------------------------------
__global__ void vq_split_emb(const float* __restrict__ src) {
    if (blockIdx.x == 0 && threadIdx.x == 0) d_count = 0;
    int row  = blockIdx.x * 8 + (threadIdx.x >> 5);
    int lane = threadIdx.x & 31;
    const float4* x4 = (const float4*)(src + (size_t)row * DD + lane * 8);
    float4 v0 = x4[0], v1 = x4[1];
    float vv[8] = {v0.x, v0.y, v0.z, v0.w, v1.x, v1.y, v1.z, v1.w};
    __half h0[8], h1[8];
    float s = 0.f, s0 = 0.f, s1 = 0.f;
#pragma unroll
    for (int i = 0; i < 8; ++i) {
        h0[i] = __float2half_rn(vv[i]);
        float f0 = __half2float(h0[i]);
        h1[i] = __float2half_rn(vv[i] - f0);
        float f1 = __half2float(h1[i]);
        s  += vv[i] * vv[i];
        s0 += f0 * f0;
        s1 += f1 * f1;
    }
#pragma unroll
    for (int o = 16; o; o >>= 1) {
        s  += __shfl_xor_sync(0xffffffffu, s, o);
        s0 += __shfl_xor_sync(0xffffffffu, s0, o);
        s1 += __shfl_xor_sync(0xffffffffu, s1, o);
    }
    if (lane == 0) {
        d_half_norm[row] = 0.5f * s;
        atomicMax(&d_b0max_bits, __float_as_int(sqrtf(s0)));
        atomicMax(&d_remax_bits, __float_as_int(sqrtf(s1)));
    }
    *(uint4*)(d_B + (size_t)row * 512 + lane * 8)       = *(uint4*)h0;
    *(uint4*)(d_B + (size_t)row * 512 + 256 + lane * 8) = *(uint4*)h1;
    int g = blockIdx.x * blockDim.x + threadIdx.x;
    if (g < KK) d_usage[g] = 0;
}

// ---------------------------------------------------------------------------
// Pass 1: fused z_e split (prologue) + single-product (a0*b0) GEMM
// + min1/min2 + certification.  CTAN=128, warp tile 64x32, occupancy 2.
// ---------------------------------------------------------------------------
__device__ __forceinline__ void p1_issue(uint32_t sb, int g2, int tid) {
    const int t2 = g2 >> 2, seg = g2 & 3;               // b0 segs 0-3
    const __half* src = d_B + (size_t)(t2 * P1_CTAN) * 512 + seg * 64;
    uint32_t db = sb + P1_OFF_B + (uint32_t)(g2 & 1) * 16384;
#pragma unroll
    for (int j = 0; j < 4; ++j) {
        int i = tid + 256 * j;                          // 0..1023 16B units
        int r = i >> 3, u = i & 7;
        const void* gp = (const void*)(src + (size_t)r * 512 + u * 8);
        uint32_t off = (uint32_t)(((r >> 3) << 10) + ((r & 7) << 7) + (u << 4));
        asm volatile("cp.async.cg.shared.global [%0], [%1], 16;"
                     :: "r"(db + SWZ(off)), "l"(gp));
    }
    asm volatile("cp.async.commit_group;" ::: "memory");
}

__global__ __launch_bounds__(256, 2) void vq_pass1_kernel(const float* __restrict__ ze) {
    extern __shared__ __align__(1024) char smem[];
    const uint32_t sb = smem_u32(smem);
    const int tid  = threadIdx.x;
    const int lane = tid & 31, wid = tid >> 5;
    const int wm = wid >> 2, wn = wid & 3;              // 2m x 4n warp grid
    const int m0 = blockIdx.x * CTAM;
    float* shn = (float*)(smem + P1_OFF_HN);

    // ---- Fused prologue: split this CTA's 128 z_e rows (fp32 -> a0,a1).
    // Thread t: row r = t>>1, column half h = t&1 (128 floats).
    // a0 -> swizzled smem planes (+d_A for rescue); a1 -> d_A; norms via partner shfl.
    {
        const int r  = tid >> 1;
        const int h  = tid & 1;
        const int R  = m0 + r;
        const float4* src = (const float4*)(ze + (size_t)R * DD + h * 128);
        __half* gA0 = d_A + (size_t)R * 512 + h * 128;
        __half* gA1 = gA0 + 256;
        float s0 = 0.f, s1 = 0.f;
#pragma unroll
        for (int j = 0; j < 16; ++j) {                  // 8 halves (uint4) per j
            float4 va = src[j * 2], vb = src[j * 2 + 1];
            float vv[8] = {va.x, va.y, va.z, va.w, vb.x, vb.y, vb.z, vb.w};
            __half h0[8], h1[8];
#pragma unroll
            for (int i = 0; i < 8; ++i) {
                h0[i] = __float2half_rn(vv[i]);
                float f0 = __half2float(h0[i]);
                h1[i] = __float2half_rn(vv[i] - f0);
                float f1 = __half2float(h1[i]);
                s0 += f0 * f0;
                s1 += f1 * f1;
            }
            *(uint4*)(gA0 + j * 8) = *(uint4*)h0;
            *(uint4*)(gA1 + j * 8) = *(uint4*)h1;
            // a0 -> smem plane: global col c0 = h*128 + j*8
            int c0 = h * 128 + j * 8;
            int p = c0 >> 6, cip = c0 & 63;
            uint32_t off = (uint32_t)(p * 16384 + ((r >> 3) << 10) + ((r & 7) << 7)
                                      + cip * 2);
            *(uint4*)(smem + P1_OFF_A + SWZ(off)) = *(uint4*)h0;
        }
        float o0 = __shfl_xor_sync(0xffffffffu, s0, 1);
        float o1 = __shfl_xor_sync(0xffffffffu, s1, 1);
        if (h == 0) {
            d_a0norm[R] = sqrtf(s0 + o0);
            d_rxnorm[R] = sqrtf(s1 + o1);
        }
    }

    float acc[4][4][4];
#pragma unroll
    for (int mi = 0; mi < 4; ++mi)
#pragma unroll
        for (int ni = 0; ni < 4; ++ni)
#pragma unroll
            for (int k = 0; k < 4; ++k) acc[mi][ni][k] = 0.f;
    float m1[8], m2[8];
    int   i1[8];
#pragma unroll
    for (int i = 0; i < 8; ++i) { m1[i] = 3.4028235e38f; m2[i] = 3.4028235e38f; i1[i] = 0; }

    p1_issue(sb, 0, tid);

    const int NITER = (KK / P1_CTAN) * 4;               // 64 tiles x 4 chunks = 256
    for (int g = 0; g < NITER; ++g) {
        __syncthreads();
        if (g + 1 < NITER) {
            p1_issue(sb, g + 1, tid);
            asm volatile("cp.async.wait_group 1;" ::: "memory");
        } else {
            asm volatile("cp.async.wait_group 0;" ::: "memory");
        }
        __syncthreads();

        const int tile = g >> 2, c = g & 3;
        if (c == 0 && tid < 128) shn[tid] = d_half_norm[tile * P1_CTAN + tid];

        const uint32_t ab = sb + P1_OFF_A + (uint32_t)c * 16384;
        const uint32_t bb = sb + P1_OFF_B + (uint32_t)(g & 1) * 16384;
#pragma unroll
        for (int s = 0; s < 4; ++s) {
            uint32_t a[4][4];
#pragma unroll
            for (int mi = 0; mi < 4; ++mi) {
                int r = wm * 64 + mi * 16 + (lane & 7) + ((lane >> 3) & 1) * 8;
                int u = s * 2 + (lane >> 4);
                uint32_t off = ((uint32_t)(r >> 3) << 10) + ((uint32_t)(r & 7) << 7)
                             + ((uint32_t)u << 4);
                asm volatile("ldmatrix.sync.aligned.m8n8.x4.shared.b16 {%0,%1,%2,%3}, [%4];"
                    : "=r"(a[mi][0]), "=r"(a[mi][1]), "=r"(a[mi][2]), "=r"(a[mi][3])
                    : "r"(ab + SWZ(off)));
            }
            uint32_t b[4][2];
#pragma unroll
            for (int nq = 0; nq < 2; ++nq) {
                int r = wn * 32 + nq * 16 + (lane & 7) + ((lane >> 4) & 1) * 8;
                int u = s * 2 + ((lane >> 3) & 1);
                uint32_t off = ((uint32_t)(r >> 3) << 10) + ((uint32_t)(r & 7) << 7)
                             + ((uint32_t)u << 4);
                asm volatile("ldmatrix.sync.aligned.m8n8.x4.shared.b16 {%0,%1,%2,%3}, [%4];"
                    : "=r"(b[2*nq][0]), "=r"(b[2*nq][1]), "=r"(b[2*nq+1][0]), "=r"(b[2*nq+1][1])
                    : "r"(bb + SWZ(off)));
            }
#pragma unroll
            for (int mi = 0; mi < 4; ++mi)
#pragma unroll
                for (int ni = 0; ni < 4; ++ni)
                    asm volatile("mma.sync.aligned.m16n8k16.row.col.f32.f16.f16.f32 "
                        "{%0,%1,%2,%3}, {%4,%5,%6,%7}, {%8,%9}, {%0,%1,%2,%3};"
                        : "+f"(acc[mi][ni][0]), "+f"(acc[mi][ni][1]),
                          "+f"(acc[mi][ni][2]), "+f"(acc[mi][ni][3])
                        : "r"(a[mi][0]), "r"(a[mi][1]), "r"(a[mi][2]), "r"(a[mi][3]),
                          "r"(b[ni][0]), "r"(b[ni][1]));
        }

        if (c == 3) {
#pragma unroll
            for (int ni = 0; ni < 4; ++ni)
#pragma unroll
                for (int c2 = 0; c2 < 2; ++c2) {
                    int coll = wn * 32 + ni * 8 + (lane & 3) * 2 + c2;
                    float hv = shn[coll];
                    int gcol = tile * P1_CTAN + coll;
#pragma unroll
                    for (int mi = 0; mi < 4; ++mi)
#pragma unroll
                        for (int h = 0; h < 2; ++h) {
                            float sc = hv - acc[mi][ni][h * 2 + c2];
                            int rm = mi * 2 + h;
                            if (sc < m1[rm]) { m2[rm] = m1[rm]; m1[rm] = sc; i1[rm] = gcol; }
                            else if (sc < m2[rm]) { m2[rm] = sc; }
                            acc[mi][ni][h * 2 + c2] = 0.f;
                        }
                }
        }
    }

    // reduce (m1,i1,m2) per row; scratch aliases B ring
    __syncthreads();
    float* rv = (float*)(smem + P1_OFF_RV);
    int*   ri = (int*)(smem + P1_OFF_RI);
    float* r2 = (float*)(smem + P1_OFF_R2);
#pragma unroll
    for (int rm = 0; rm < 8; ++rm) {
        float v = m1[rm], v2 = m2[rm];
        int ix = i1[rm];
#pragma unroll
        for (int o = 1; o <= 2; o <<= 1) {
            float ov  = __shfl_xor_sync(0xffffffffu, v, o);
            int   oi  = __shfl_xor_sync(0xffffffffu, ix, o);
            float ov2 = __shfl_xor_sync(0xffffffffu, v2, o);
            if (ov < v || (ov == v && oi < ix)) {
                v2 = fminf(v, ov2); v = ov; ix = oi;
            } else {
                v2 = fminf(v2, ov);
            }
        }
        if ((lane & 3) == 0) {
            int ml = wm * 64 + (rm >> 1) * 16 + (rm & 1) * 8 + (lane >> 2);
            rv[ml * 4 + wn] = v; ri[ml * 4 + wn] = ix; r2[ml * 4 + wn] = v2;
        }
    }
    __syncthreads();
    if (tid < 128) {
        float v = rv[tid * 4], v2 = r2[tid * 4];
        int ix = ri[tid * 4];
#pragma unroll
        for (int w = 1; w < 4; ++w) {
            float ov = rv[tid * 4 + w], ov2 = r2[tid * 4 + w];
            int oi = ri[tid * 4 + w];
            if (ov < v || (ov == v && oi < ix)) {
                v2 = fminf(v, ov2); v = ov; ix = oi;
            } else {
                v2 = fminf(v2, ov);
            }
        }
        const int row = m0 + tid;
        d_indices[row] = ix;
        // certified Cauchy-Schwarz bound with exact split-part norms:
        // |score_p1 - score_rescue| <= ||a0||*max||b1|| + ||a1||*max||b0||
        float thr = (d_a0norm[row] * __int_as_float(d_remax_bits)
                   + d_rxnorm[row] * __int_as_float(d_b0max_bits)) * 1.01f + 1e-4f;
        if (!(v2 - v > thr)) {
            int pos = atomicAdd(&d_count, 1);
            d_amb[pos] = row;
        }
    }
}

// ---------------------------------------------------------------------------
// Rescue: exact 3-product GEMM over ambiguous rows, N-split by 16 (512 codes)
// ---------------------------------------------------------------------------
__device__ __forceinline__ void rs_issue_b(uint32_t sb, int g2, int ns, int tid) {
    const int t2 = g2 / 12;
    const int c2 = g2 - t2 * 12;
    const int seg = (c2 < 8) ? c2 : (c2 - 8);
    const __half* src = d_B + (size_t)(ns * 512 + t2 * CTAN) * 512 + seg * 64;
    uint32_t db = sb + RS_OFF_B + (uint32_t)(g2 % 3) * 32768;
#pragma unroll
    for (int j = 0; j < 8; ++j) {
        int i = tid + 256 * j;
        int r = i >> 3, u = i & 7;
        const void* gp = (const void*)(src + (size_t)r * 512 + u * 8);
        uint32_t off = (uint32_t)(((r >> 3) << 10) + ((r & 7) << 7) + (u << 4));
        asm volatile("cp.async.cg.shared.global [%0], [%1], 16;"
                     :: "r"(db + SWZ(off)), "l"(gp));
    }
    asm volatile("cp.async.commit_group;" ::: "memory");
}

__global__ __launch_bounds__(256, 1) void vq_rescue_kernel() {
    const int count = d_count;
    const int mt = blockIdx.x >> 4;
    const int ns = blockIdx.x & 15;
    const int m0 = mt * CTAM;
    if (m0 >= count) return;

    extern __shared__ __align__(1024) char smem[];
    const uint32_t sb = smem_u32(smem);
    const int tid  = threadIdx.x;
    const int lane = tid & 31, wid = tid >> 5;
    const int wm = wid >> 2, wn = wid & 3;
    float* shn = (float*)(smem + RS_OFF_HN);

    // A resident: gather ambiguous rows, both planes
    {
#pragma unroll
        for (int q = 0; q < 32; ++q) {
            int i = tid + 256 * q;            // 0..8191 16B units
            int p = i >> 10;
            int r = (i >> 3) & 127;
            int u = i & 7;
            int slot = m0 + r;
            int row = d_amb[slot < count ? slot : count - 1];
            uint4 v = *(const uint4*)(d_A + (size_t)row * 512 + p * 64 + u * 8);
            uint32_t off = (uint32_t)(p * 16384 + ((r >> 3) << 10) + ((r & 7) << 7) + (u << 4));
            *(uint4*)(smem + RS_OFF_A + SWZ(off)) = v;
        }
    }

    float acc[4][8][4];
#pragma unroll
    for (int mi = 0; mi < 4; ++mi)
#pragma unroll
        for (int ni = 0; ni < 8; ++ni)
#pragma unroll
            for (int k = 0; k < 4; ++k) acc[mi][ni][k] = 0.f;
    float minv[8];
    int   mini[8];
#pragma unroll
    for (int i = 0; i < 8; ++i) { minv[i] = 3.4028235e38f; mini[i] = 0; }

    rs_issue_b(sb, 0, ns, tid);
    rs_issue_b(sb, 1, ns, tid);

    const int NITER = 2 * 12;                 // 2 tiles per split
    int tile = 0, c = 0;
    for (int g = 0; g < NITER; ++g) {
        if (g + 1 < NITER) {
            asm volatile("cp.async.wait_group 1;" ::: "memory");
        } else {
            asm volatile("cp.async.wait_group 0;" ::: "memory");
        }
        __syncthreads();
        if (g + 2 < NITER) rs_issue_b(sb, g + 2, ns, tid);

        if (c == 0) shn[tid] = d_half_norm[ns * 512 + tile * CTAN + tid];

        const int apl = (c < 8) ? (c & 3) : (c - 4);
        const uint32_t ab = sb + RS_OFF_A + (uint32_t)apl * 16384;
        const uint32_t bb = sb + RS_OFF_B + (uint32_t)(g % 3) * 32768;
#pragma unroll
        for (int s = 0; s < 4; ++s) {
            uint32_t a[4][4];
#pragma unroll
            for (int mi = 0; mi < 4; ++mi) {
                int r = wm * 64 + mi * 16 + (lane & 7) + ((lane >> 3) & 1) * 8;
                int u = s * 2 + (lane >> 4);
                uint32_t off = ((uint32_t)(r >> 3) << 10) + ((uint32_t)(r & 7) << 7)
                             + ((uint32_t)u << 4);
                asm volatile("ldmatrix.sync.aligned.m8n8.x4.shared.b16 {%0,%1,%2,%3}, [%4];"
                    : "=r"(a[mi][0]), "=r"(a[mi][1]), "=r"(a[mi][2]), "=r"(a[mi][3])
                    : "r"(ab + SWZ(off)));
            }
            uint32_t b[8][2];
#pragma unroll
            for (int nq = 0; nq < 4; ++nq) {
                int r = wn * 64 + nq * 16 + (lane & 7) + ((lane >> 4) & 1) * 8;
                int u = s * 2 + ((lane >> 3) & 1);
                uint32_t off = ((uint32_t)(r >> 3) << 10) + ((uint32_t)(r & 7) << 7)
                             + ((uint32_t)u << 4);
                asm volatile("ldmatrix.sync.aligned.m8n8.x4.shared.b16 {%0,%1,%2,%3}, [%4];"
                    : "=r"(b[2*nq][0]), "=r"(b[2*nq][1]), "=r"(b[2*nq+1][0]), "=r"(b[2*nq+1][1])
                    : "r"(bb + SWZ(off)));
            }
#pragma unroll
            for (int mi = 0; mi < 4; ++mi)
#pragma unroll
                for (int ni = 0; ni < 8; ++ni)
                    asm volatile("mma.sync.aligned.m16n8k16.row.col.f32.f16.f16.f32 "
                        "{%0,%1,%2,%3}, {%4,%5,%6,%7}, {%8,%9}, {%0,%1,%2,%3};"
                        : "+f"(acc[mi][ni][0]), "+f"(acc[mi][ni][1]),
                          "+f"(acc[mi][ni][2]), "+f"(acc[mi][ni][3])
                        : "r"(a[mi][0]), "r"(a[mi][1]), "r"(a[mi][2]), "r"(a[mi][3]),
                          "r"(b[ni][0]), "r"(b[ni][1]));
        }

        if (c == 11) {
#pragma unroll
            for (int ni = 0; ni < 8; ++ni)
#pragma unroll
                for (int c2 = 0; c2 < 2; ++c2) {
                    int coll = wn * 64 + ni * 8 + (lane & 3) * 2 + c2;
                    float hv = shn[coll];
                    int gcol = ns * 512 + tile * CTAN + coll;
#pragma unroll
                    for (int mi = 0; mi < 4; ++mi)
#pragma unroll
                        for (int h = 0; h < 2; ++h) {
                            float sc = hv - acc[mi][ni][h * 2 + c2];
                            int rm = mi * 2 + h;
                            if (sc < minv[rm]) { minv[rm] = sc; mini[rm] = gcol; }
                            acc[mi][ni][h * 2 + c2] = 0.f;
                        }
                }
            tile++; c = 0;
        } else {
            c++;
        }
    }

    __syncthreads();
    float* rv = (float*)(smem + RS_OFF_RV);
    int*   ri = (int*)(smem + RS_OFF_RI);
#pragma unroll
    for (int rm = 0; rm < 8; ++rm) {
        float v = minv[rm]; int ix = mini[rm];
#pragma unroll
        for (int o = 1; o <= 2; o <<= 1) {
            float ov = __shfl_xor_sync(0xffffffffu, v, o);
            int   oi = __shfl_xor_sync(0xffffffffu, ix, o);
            if (ov < v || (ov == v && oi < ix)) { v = ov; ix = oi; }
        }
        if ((lane & 3) == 0) {
            int ml = wm * 64 + (rm >> 1) * 16 + (rm & 1) * 8 + (lane >> 2);
            rv[ml * 4 + wn] = v;
            ri[ml * 4 + wn] = ix;
        }
    }
    __syncthreads();
    if (tid < 128) {
        float v = rv[tid * 4]; int ix = ri[tid * 4];
#pragma unroll
        for (int w = 1; w < 4; ++w) {
            float ov = rv[tid * 4 + w]; int oi = ri[tid * 4 + w];
            if (ov < v || (ov == v && oi < ix)) { v = ov; ix = oi; }
        }
        int slot = m0 + tid;
        if (slot < count) {
            d_resc_v[ns * NN + slot] = v;
            d_resc_i[ns * NN + slot] = ix;
        }
    }
}

__global__ void vq_amb_merge_kernel() {
    int i = blockIdx.x * blockDim.x + threadIdx.x;
    if (i < d_count) {
        float v = d_resc_v[i]; int ix = d_resc_i[i];
#pragma unroll
        for (int s = 1; s < NSPLIT; ++s) {
            float ov = d_resc_v[s * NN + i]; int oi = d_resc_i[s * NN + i];
            if (ov < v || (ov == v && oi < ix)) { v = ov; ix = oi; }
        }
        d_indices[d_amb[i]] = ix;
    }
}

// ---------------------------------------------------------------------------
// gather (+ usage histogram) + stats
// ---------------------------------------------------------------------------
__global__ void vq_gather_kernel(const float* __restrict__ ze,
                                 const float* __restrict__ emb,
                                 float* __restrict__ out) {
    int t = threadIdx.x;
    int m = blockIdx.x * 4 + (t >> 6);
    int l = t & 63;
    int idx = d_indices[m];
    float4 e = *(const float4*)(emb + (size_t)idx * DD + l * 4);
    float4 x = *(const float4*)(ze  + (size_t)m   * DD + l * 4);
    float4 st;
    st.x = x.x + (e.x - x.x); st.y = x.y + (e.y - x.y);
    st.z = x.z + (e.z - x.z); st.w = x.w + (e.w - x.w);
    *(float4*)(out + (size_t)m * DD + l * 4) = st;
    *(float4*)(out + (size_t)NN * DD + (size_t)m * DD + l * 4) = e;
    if (l == 0) {
        out[(size_t)2 * NN * DD + m] = (float)idx;
        atomicAdd(&d_usage[idx], 1);
    }
}

__global__ void vq_stats_kernel(float* __restrict__ out) {
    __shared__ float sH[32];
    __shared__ int   sD[32];
    int t = threadIdx.x;
    float H = 0.f; int dead = 0;
    const float inv_total = 1.0f / (float)NN;
    for (int k = t; k < KK; k += 1024) {
        int u = d_usage[k];
        if (u == 0) dead++;
        else { float p = (float)u * inv_total; H += p * logf(p); }
    }
#pragma unroll
    for (int o = 16; o; o >>= 1) {
        H    += __shfl_xor_sync(0xffffffffu, H, o);
        dead += __shfl_xor_sync(0xffffffffu, dead, o);
    }
    if ((t & 31) == 0) { sH[t >> 5] = H; sD[t >> 5] = dead; }
    __syncthreads();
    if (t == 0) {
        float Ht = 0.f; int dt = 0;
        for (int w = 0; w < 32; w++) { Ht += sH[w]; dt += sD[w]; }
        size_t off = (size_t)2 * NN * DD + NN;
        out[off + 0] = expf(-Ht);
        out[off + 1] = (float)dt / (float)KK;
    }
}

// ---------------------------------------------------------------------------
extern "C" void kernel_launch(void* const* d_in, const int* in_sizes, int n_in,
                              void* d_out, int out_size) {
    const float* ze  = (const float*)d_in[0];
    const float* emb = (const float*)d_in[1];
    float* out = (float*)d_out;

    cudaFuncSetAttribute(vq_pass1_kernel, cudaFuncAttributeMaxDynamicSharedMemorySize,
                         P1_SMEM);
    cudaFuncSetAttribute(vq_rescue_kernel, cudaFuncAttributeMaxDynamicSharedMemorySize,
                         RS_SMEM);

    vq_split_emb<<<KK / 8, 256>>>(emb);
    vq_pass1_kernel<<<NN / CTAM, 256, P1_SMEM>>>(ze);
    vq_rescue_kernel<<<(NN / CTAM) * NSPLIT, 256, RS_SMEM>>>();
    vq_amb_merge_kernel<<<NN / 256, 256>>>();
    vq_gather_kernel<<<NN / 4, 256>>>(ze, emb, out);
    vq_stats_kernel<<<1, 1024>>>(out);
}

// round 14
// speedup vs baseline: 1.0424x; 1.0424x over previous
#include <cuda_runtime.h>
#include <cuda_fp16.h>
#include <cstdint>

#define DD   256
#define KK   8192
#define NN   32768
#define CTAM 128
#define NSPLIT 16                 // rescue N-splits (512 codes each)

// ---- pass1 smem layout (A = a0 only, 4 planes; CTAN=128; 2-stage 16KB B ring)
#define P1_CTAN   128
#define P1_OFF_A  0               // 4 x 16384 = 65536
#define P1_OFF_B  65536           // 2 stages x 16384 = 32768
#define P1_OFF_HN 98304           // 128 floats
#define P1_SMEM   98816
#define P1_OFF_RV P1_OFF_B
#define P1_OFF_RI (P1_OFF_B + 2048)
#define P1_OFF_R2 (P1_OFF_B + 4096)

// ---- rescue smem layout (A = [a0|a1], 8 planes; 3-stage 32KB ring; CTAN=256)
#define CTAN 256
#define RS_OFF_A  0               // 8 x 16384 = 131072
#define RS_OFF_B  131072          // 3 stages x 32768
#define RS_OFF_HN 229376
#define RS_SMEM   230400
#define RS_OFF_RV RS_OFF_B
#define RS_OFF_RI (RS_OFF_B + 2048)

#define SWZ(x) ((x) ^ (((x) >> 3) & 0x70))

// Scratch (no allocations allowed)
__device__ float d_half_norm[KK];
__device__ float d_a0norm[NN];
__device__ float d_rxnorm[NN];
__device__ int   d_usage[KK];
__device__ int   d_indices[NN];
__device__ int   d_count;
__device__ int   d_b0max_bits;
__device__ int   d_remax_bits;
__device__ int   d_amb[NN];
__device__ float d_resc_v[NSPLIT * NN];
__device__ int   d_resc_i[NSPLIT * NN];
__device__ float d_partH[8];
__device__ int   d_partD[8];
__device__ __half d_A[(size_t)NN * 512];   // [a0(256) | a1(256)] per row
__device__ __half d_B[(size_t)KK * 512];   // [b0(256) | b1(256)] per row

__device__ __forceinline__ uint32_t smem_u32(const void* p) {
    uint32_t a;
    asm("{ .reg .u64 t; cvta.to.shared.u64 t, %1; cvt.u32.u64 %0, t; }" : "=r"(a) : "l"(p));
    return a;
}

// ---------------------------------------------------------------------------
// Fused splits: exact 2-way fp16 split + exact split-part norms (warp per row)
// ---------------------------------------------------------------------------
__global__ void vq_split_ze(const float* __restrict__ src) {
    if (blockIdx.x == 0 && threadIdx.x == 0) {
        d_count = 0; d_b0max_bits = 0; d_remax_bits = 0;
    }
    int row  = blockIdx.x * 8 + (threadIdx.x >> 5);
    int lane = threadIdx.x & 31;
    const float4* x4 = (const float4*)(src + (size_t)row * DD + lane * 8);
    float4 v0 = x4[0], v1 = x4[1];
    float vv[8] = {v0.x, v0.y, v0.z, v0.w, v1.x, v1.y, v1.z, v1.w};
    __half h0[8], h1[8];
    float s0 = 0.f, s1 = 0.f;
#pragma unroll
    for (int i = 0; i < 8; ++i) {
        h0[i] = __float2half_rn(vv[i]);
        float f0 = __half2float(h0[i]);
        h1[i] = __float2half_rn(vv[i] - f0);
        float f1 = __half2float(h1[i]);
        s0 += f0 * f0;
        s1 += f1 * f1;
    }
#pragma unroll
    for (int o = 16; o; o >>= 1) {
        s0 += __shfl_xor_sync(0xffffffffu, s0, o);
        s1 += __shfl_xor_sync(0xffffffffu, s1, o);
    }
    if (lane == 0) { d_a0norm[row] = sqrtf(s0); d_rxnorm[row] = sqrtf(s1); }
    *(uint4*)(d_A + (size_t)row * 512 + lane * 8)       = *(uint4*)h0;
    *(uint4*)(d_A + (size_t)row * 512 + 256 + lane * 8) = *(uint4*)h1;
}
__global__ void vq_split_emb(const float* __restrict__ src) {
    int row  = blockIdx.x * 8 + (threadIdx.x >> 5);
    int lane = threadIdx.x & 31;
    const float4* x4 = (const float4*)(src + (size_t)row * DD + lane * 8);
    float4 v0 = x4[0], v1 = x4[1];
    float vv[8] = {v0.x, v0.y, v0.z, v0.w, v1.x, v1.y, v1.z, v1.w};
    __half h0[8], h1[8];
    float s = 0.f, s0 = 0.f, s1 = 0.f;
#pragma unroll
    for (int i = 0; i < 8; ++i) {
        h0[i] = __float2half_rn(vv[i]);
        float f0 = __half2float(h0[i]);
        h1[i] = __float2half_rn(vv[i] - f0);
        float f1 = __half2float(h1[i]);
        s  += vv[i] * vv[i];
        s0 += f0 * f0;
        s1 += f1 * f1;
    }
#pragma unroll
    for (int o = 16; o; o >>= 1) {
        s  += __shfl_xor_sync(0xffffffffu, s, o);
        s0 += __shfl_xor_sync(0xffffffffu, s0, o);
        s1 += __shfl_xor_sync(0xffffffffu, s1, o);
    }
    if (lane == 0) {
        d_half_norm[row] = 0.5f * s;
        atomicMax(&d_b0max_bits, __float_as_int(sqrtf(s0)));
        atomicMax(&d_remax_bits, __float_as_int(sqrtf(s1)));
    }
    *(uint4*)(d_B + (size_t)row * 512 + lane * 8)       = *(uint4*)h0;
    *(uint4*)(d_B + (size_t)row * 512 + 256 + lane * 8) = *(uint4*)h1;
    int g = blockIdx.x * blockDim.x + threadIdx.x;
    if (g < KK) d_usage[g] = 0;
}

// ---------------------------------------------------------------------------
// Pass 1: single-product (a0*b0) GEMM + min1/min2 + certification.
// CTAN=128, warp tile 64x32, occupancy 2.   (proven R9 config)
// ---------------------------------------------------------------------------
__device__ __forceinline__ void p1_issue(uint32_t sb, int g2, int tid) {
    const int t2 = g2 >> 2, seg = g2 & 3;               // b0 segs 0-3
    const __half* src = d_B + (size_t)(t2 * P1_CTAN) * 512 + seg * 64;
    uint32_t db = sb + P1_OFF_B + (uint32_t)(g2 & 1) * 16384;
#pragma unroll
    for (int j = 0; j < 4; ++j) {
        int i = tid + 256 * j;                          // 0..1023 16B units
        int r = i >> 3, u = i & 7;
        const void* gp = (const void*)(src + (size_t)r * 512 + u * 8);
        uint32_t off = (uint32_t)(((r >> 3) << 10) + ((r & 7) << 7) + (u << 4));
        asm volatile("cp.async.cg.shared.global [%0], [%1], 16;"
                     :: "r"(db + SWZ(off)), "l"(gp));
    }
    asm volatile("cp.async.commit_group;" ::: "memory");
}

__global__ __launch_bounds__(256, 2) void vq_pass1_kernel() {
    extern __shared__ __align__(1024) char smem[];
    const uint32_t sb = smem_u32(smem);
    const int tid  = threadIdx.x;
    const int lane = tid & 31, wid = tid >> 5;
    const int wm = wid >> 2, wn = wid & 3;              // 2m x 4n warp grid
    const int m0 = blockIdx.x * CTAM;
    float* shn = (float*)(smem + P1_OFF_HN);

    // A resident: a0 only, 4 planes
    {
        const __half* Arow = d_A + (size_t)m0 * 512;
#pragma unroll
        for (int q = 0; q < 16; ++q) {
            int i = tid + 256 * q;            // 0..4095 16B units
            int p = i >> 10;
            int r = (i >> 3) & 127;
            int u = i & 7;
            uint4 v = *(const uint4*)(Arow + (size_t)r * 512 + p * 64 + u * 8);
            uint32_t off = (uint32_t)(p * 16384 + ((r >> 3) << 10) + ((r & 7) << 7) + (u << 4));
            *(uint4*)(smem + P1_OFF_A + SWZ(off)) = v;
        }
    }

    float acc[4][4][4];
#pragma unroll
    for (int mi = 0; mi < 4; ++mi)
#pragma unroll
        for (int ni = 0; ni < 4; ++ni)
#pragma unroll
            for (int k = 0; k < 4; ++k) acc[mi][ni][k] = 0.f;
    float m1[8], m2[8];
    int   i1[8];
#pragma unroll
    for (int i = 0; i < 8; ++i) { m1[i] = 3.4028235e38f; m2[i] = 3.4028235e38f; i1[i] = 0; }

    p1_issue(sb, 0, tid);

    const int NITER = (KK / P1_CTAN) * 4;               // 64 tiles x 4 chunks = 256
    for (int g = 0; g < NITER; ++g) {
        __syncthreads();
        if (g + 1 < NITER) {
            p1_issue(sb, g + 1, tid);
            asm volatile("cp.async.wait_group 1;" ::: "memory");
        } else {
            asm volatile("cp.async.wait_group 0;" ::: "memory");
        }
        __syncthreads();

        const int tile = g >> 2, c = g & 3;
        if (c == 0 && tid < 128) shn[tid] = d_half_norm[tile * P1_CTAN + tid];

        const uint32_t ab = sb + P1_OFF_A + (uint32_t)c * 16384;
        const uint32_t bb = sb + P1_OFF_B + (uint32_t)(g & 1) * 16384;
#pragma unroll
        for (int s = 0; s < 4; ++s) {
            uint32_t a[4][4];
#pragma unroll
            for (int mi = 0; mi < 4; ++mi) {
                int r = wm * 64 + mi * 16 + (lane & 7) + ((lane >> 3) & 1) * 8;
                int u = s * 2 + (lane >> 4);
                uint32_t off = ((uint32_t)(r >> 3) << 10) + ((uint32_t)(r & 7) << 7)
                             + ((uint32_t)u << 4);
                asm volatile("ldmatrix.sync.aligned.m8n8.x4.shared.b16 {%0,%1,%2,%3}, [%4];"
                    : "=r"(a[mi][0]), "=r"(a[mi][1]), "=r"(a[mi][2]), "=r"(a[mi][3])
                    : "r"(ab + SWZ(off)));
            }
            uint32_t b[4][2];
#pragma unroll
            for (int nq = 0; nq < 2; ++nq) {
                int r = wn * 32 + nq * 16 + (lane & 7) + ((lane >> 4) & 1) * 8;
                int u = s * 2 + ((lane >> 3) & 1);
                uint32_t off = ((uint32_t)(r >> 3) << 10) + ((uint32_t)(r & 7) << 7)
                             + ((uint32_t)u << 4);
                asm volatile("ldmatrix.sync.aligned.m8n8.x4.shared.b16 {%0,%1,%2,%3}, [%4];"
                    : "=r"(b[2*nq][0]), "=r"(b[2*nq][1]), "=r"(b[2*nq+1][0]), "=r"(b[2*nq+1][1])
                    : "r"(bb + SWZ(off)));
            }
#pragma unroll
            for (int mi = 0; mi < 4; ++mi)
#pragma unroll
                for (int ni = 0; ni < 4; ++ni)
                    asm volatile("mma.sync.aligned.m16n8k16.row.col.f32.f16.f16.f32 "
                        "{%0,%1,%2,%3}, {%4,%5,%6,%7}, {%8,%9}, {%0,%1,%2,%3};"
                        : "+f"(acc[mi][ni][0]), "+f"(acc[mi][ni][1]),
                          "+f"(acc[mi][ni][2]), "+f"(acc[mi][ni][3])
                        : "r"(a[mi][0]), "r"(a[mi][1]), "r"(a[mi][2]), "r"(a[mi][3]),
                          "r"(b[ni][0]), "r"(b[ni][1]));
        }

        if (c == 3) {
#pragma unroll
            for (int ni = 0; ni < 4; ++ni)
#pragma unroll
                for (int c2 = 0; c2 < 2; ++c2) {
                    int coll = wn * 32 + ni * 8 + (lane & 3) * 2 + c2;
                    float hv = shn[coll];
                    int gcol = tile * P1_CTAN + coll;
#pragma unroll
                    for (int mi = 0; mi < 4; ++mi)
#pragma unroll
                        for (int h = 0; h < 2; ++h) {
                            float sc = hv - acc[mi][ni][h * 2 + c2];
                            int rm = mi * 2 + h;
                            if (sc < m1[rm]) { m2[rm] = m1[rm]; m1[rm] = sc; i1[rm] = gcol; }
                            else if (sc < m2[rm]) { m2[rm] = sc; }
                            acc[mi][ni][h * 2 + c2] = 0.f;
                        }
                }
        }
    }

    // reduce (m1,i1,m2) per row; scratch aliases B ring
    __syncthreads();
    float* rv = (float*)(smem + P1_OFF_RV);
    int*   ri = (int*)(smem + P1_OFF_RI);
    float* r2 = (float*)(smem + P1_OFF_R2);
#pragma unroll
    for (int rm = 0; rm < 8; ++rm) {
        float v = m1[rm], v2 = m2[rm];
        int ix = i1[rm];
#pragma unroll
        for (int o = 1; o <= 2; o <<= 1) {
            float ov  = __shfl_xor_sync(0xffffffffu, v, o);
            int   oi  = __shfl_xor_sync(0xffffffffu, ix, o);
            float ov2 = __shfl_xor_sync(0xffffffffu, v2, o);
            if (ov < v || (ov == v && oi < ix)) {
                v2 = fminf(v, ov2); v = ov; ix = oi;
            } else {
                v2 = fminf(v2, ov);
            }
        }
        if ((lane & 3) == 0) {
            int ml = wm * 64 + (rm >> 1) * 16 + (rm & 1) * 8 + (lane >> 2);
            rv[ml * 4 + wn] = v; ri[ml * 4 + wn] = ix; r2[ml * 4 + wn] = v2;
        }
    }
    __syncthreads();
    if (tid < 128) {
        float v = rv[tid * 4], v2 = r2[tid * 4];
        int ix = ri[tid * 4];
#pragma unroll
        for (int w = 1; w < 4; ++w) {
            float ov = rv[tid * 4 + w], ov2 = r2[tid * 4 + w];
            int oi = ri[tid * 4 + w];
            if (ov < v || (ov == v && oi < ix)) {
                v2 = fminf(v, ov2); v = ov; ix = oi;
            } else {
                v2 = fminf(v2, ov);
            }
        }
        const int row = m0 + tid;
        d_indices[row] = ix;
        // certified Cauchy-Schwarz bound with exact split-part norms:
        // |score_p1 - score_rescue| <= ||a0||*max||b1|| + ||a1||*max||b0||
        float thr = (d_a0norm[row] * __int_as_float(d_remax_bits)
                   + d_rxnorm[row] * __int_as_float(d_b0max_bits)) * 1.01f + 1e-4f;
        if (!(v2 - v > thr)) {
            int pos = atomicAdd(&d_count, 1);
            d_amb[pos] = row;
        }
    }
}

// ---------------------------------------------------------------------------
// Rescue: exact 3-product GEMM over ambiguous rows, N-split by 16 (512 codes).
// Grid 1024 blocks; each strides mt by 64 (worst-case coverage preserved).
// ---------------------------------------------------------------------------
__device__ __forceinline__ void rs_issue_b(uint32_t sb, int g2, int ns, int tid) {
    const int t2 = g2 / 12;
    const int c2 = g2 - t2 * 12;
    const int seg = (c2 < 8) ? c2 : (c2 - 8);
    const __half* src = d_B + (size_t)(ns * 512 + t2 * CTAN) * 512 + seg * 64;
    uint32_t db = sb + RS_OFF_B + (uint32_t)(g2 % 3) * 32768;
#pragma unroll
    for (int j = 0; j < 8; ++j) {
        int i = tid + 256 * j;
        int r = i >> 3, u = i & 7;
        const void* gp = (const void*)(src + (size_t)r * 512 + u * 8);
        uint32_t off = (uint32_t)(((r >> 3) << 10) + ((r & 7) << 7) + (u << 4));
        asm volatile("cp.async.cg.shared.global [%0], [%1], 16;"
                     :: "r"(db + SWZ(off)), "l"(gp));
    }
    asm volatile("cp.async.commit_group;" ::: "memory");
}

__global__ __launch_bounds__(256, 1) void vq_rescue_kernel() {
    const int count = d_count;
    const int ns  = blockIdx.x & 15;
    const int mt0 = blockIdx.x >> 4;                    // 0..63
    extern __shared__ __align__(1024) char smem[];
    const uint32_t sb = smem_u32(smem);
    const int tid  = threadIdx.x;
    const int lane = tid & 31, wid = tid >> 5;
    const int wm = wid >> 2, wn = wid & 3;
    float* shn = (float*)(smem + RS_OFF_HN);

    for (int mt = mt0; mt * CTAM < count; mt += 64) {
        const int m0 = mt * CTAM;
        __syncthreads();                                // smem reuse across mt iters

        // A resident: gather ambiguous rows, both planes
#pragma unroll
        for (int q = 0; q < 32; ++q) {
            int i = tid + 256 * q;            // 0..8191 16B units
            int p = i >> 10;
            int r = (i >> 3) & 127;
            int u = i & 7;
            int slot = m0 + r;
            int row = d_amb[slot < count ? slot : count - 1];
            uint4 v = *(const uint4*)(d_A + (size_t)row * 512 + p * 64 + u * 8);
            uint32_t off = (uint32_t)(p * 16384 + ((r >> 3) << 10) + ((r & 7) << 7) + (u << 4));
            *(uint4*)(smem + RS_OFF_A + SWZ(off)) = v;
        }

        float acc[4][8][4];
#pragma unroll
        for (int mi = 0; mi < 4; ++mi)
#pragma unroll
            for (int ni = 0; ni < 8; ++ni)
#pragma unroll
                for (int k = 0; k < 4; ++k) acc[mi][ni][k] = 0.f;
        float minv[8];
        int   mini[8];
#pragma unroll
        for (int i = 0; i < 8; ++i) { minv[i] = 3.4028235e38f; mini[i] = 0; }

        rs_issue_b(sb, 0, ns, tid);
        rs_issue_b(sb, 1, ns, tid);

        const int NITER = 2 * 12;                 // 2 tiles per split
        int tile = 0, c = 0;
        for (int g = 0; g < NITER; ++g) {
            if (g + 1 < NITER) {
                asm volatile("cp.async.wait_group 1;" ::: "memory");
            } else {
                asm volatile("cp.async.wait_group 0;" ::: "memory");
            }
            __syncthreads();
            if (g + 2 < NITER) rs_issue_b(sb, g + 2, ns, tid);

            if (c == 0) shn[tid] = d_half_norm[ns * 512 + tile * CTAN + tid];

            const int apl = (c < 8) ? (c & 3) : (c - 4);
            const uint32_t ab = sb + RS_OFF_A + (uint32_t)apl * 16384;
            const uint32_t bb = sb + RS_OFF_B + (uint32_t)(g % 3) * 32768;
#pragma unroll
            for (int s = 0; s < 4; ++s) {
                uint32_t a[4][4];
#pragma unroll
                for (int mi = 0; mi < 4; ++mi) {
                    int r = wm * 64 + mi * 16 + (lane & 7) + ((lane >> 3) & 1) * 8;
                    int u = s * 2 + (lane >> 4);
                    uint32_t off = ((uint32_t)(r >> 3) << 10) + ((uint32_t)(r & 7) << 7)
                                 + ((uint32_t)u << 4);
                    asm volatile("ldmatrix.sync.aligned.m8n8.x4.shared.b16 {%0,%1,%2,%3}, [%4];"
                        : "=r"(a[mi][0]), "=r"(a[mi][1]), "=r"(a[mi][2]), "=r"(a[mi][3])
                        : "r"(ab + SWZ(off)));
                }
                uint32_t b[8][2];
#pragma unroll
                for (int nq = 0; nq < 4; ++nq) {
                    int r = wn * 64 + nq * 16 + (lane & 7) + ((lane >> 4) & 1) * 8;
                    int u = s * 2 + ((lane >> 3) & 1);
                    uint32_t off = ((uint32_t)(r >> 3) << 10) + ((uint32_t)(r & 7) << 7)
                                 + ((uint32_t)u << 4);
                    asm volatile("ldmatrix.sync.aligned.m8n8.x4.shared.b16 {%0,%1,%2,%3}, [%4];"
                        : "=r"(b[2*nq][0]), "=r"(b[2*nq][1]), "=r"(b[2*nq+1][0]), "=r"(b[2*nq+1][1])
                        : "r"(bb + SWZ(off)));
                }
#pragma unroll
                for (int mi = 0; mi < 4; ++mi)
#pragma unroll
                    for (int ni = 0; ni < 8; ++ni)
                        asm volatile("mma.sync.aligned.m16n8k16.row.col.f32.f16.f16.f32 "
                            "{%0,%1,%2,%3}, {%4,%5,%6,%7}, {%8,%9}, {%0,%1,%2,%3};"
                            : "+f"(acc[mi][ni][0]), "+f"(acc[mi][ni][1]),
                              "+f"(acc[mi][ni][2]), "+f"(acc[mi][ni][3])
                            : "r"(a[mi][0]), "r"(a[mi][1]), "r"(a[mi][2]), "r"(a[mi][3]),
                              "r"(b[ni][0]), "r"(b[ni][1]));
            }

            if (c == 11) {
#pragma unroll
                for (int ni = 0; ni < 8; ++ni)
#pragma unroll
                    for (int c2 = 0; c2 < 2; ++c2) {
                        int coll = wn * 64 + ni * 8 + (lane & 3) * 2 + c2;
                        float hv = shn[coll];
                        int gcol = ns * 512 + tile * CTAN + coll;
#pragma unroll
                        for (int mi = 0; mi < 4; ++mi)
#pragma unroll
                            for (int h = 0; h < 2; ++h) {
                                float sc = hv - acc[mi][ni][h * 2 + c2];
                                int rm = mi * 2 + h;
                                if (sc < minv[rm]) { minv[rm] = sc; mini[rm] = gcol; }
                                acc[mi][ni][h * 2 + c2] = 0.f;
                            }
                    }
                tile++; c = 0;
            } else {
                c++;
            }
        }

        __syncthreads();
        float* rv = (float*)(smem + RS_OFF_RV);
        int*   ri = (int*)(smem + RS_OFF_RI);
#pragma unroll
        for (int rm = 0; rm < 8; ++rm) {
            float v = minv[rm]; int ix = mini[rm];
#pragma unroll
            for (int o = 1; o <= 2; o <<= 1) {
                float ov = __shfl_xor_sync(0xffffffffu, v, o);
                int   oi = __shfl_xor_sync(0xffffffffu, ix, o);
                if (ov < v || (ov == v && oi < ix)) { v = ov; ix = oi; }
            }
            if ((lane & 3) == 0) {
                int ml = wm * 64 + (rm >> 1) * 16 + (rm & 1) * 8 + (lane >> 2);
                rv[ml * 4 + wn] = v;
                ri[ml * 4 + wn] = ix;
            }
        }
        __syncthreads();
        if (tid < 128) {
            float v = rv[tid * 4]; int ix = ri[tid * 4];
#pragma unroll
            for (int w = 1; w < 4; ++w) {
                float ov = rv[tid * 4 + w]; int oi = ri[tid * 4 + w];
                if (ov < v || (ov == v && oi < ix)) { v = ov; ix = oi; }
            }
            int slot = m0 + tid;
            if (slot < count) {
                d_resc_v[ns * NN + slot] = v;
                d_resc_i[ns * NN + slot] = ix;
            }
        }
    }
}

__global__ void vq_amb_merge_kernel() {
    int i = blockIdx.x * blockDim.x + threadIdx.x;
    if (i < d_count) {
        float v = d_resc_v[i]; int ix = d_resc_i[i];
#pragma unroll
        for (int s = 1; s < NSPLIT; ++s) {
            float ov = d_resc_v[s * NN + i]; int oi = d_resc_i[s * NN + i];
            if (ov < v || (ov == v && oi < ix)) { v = ov; ix = oi; }
        }
        d_indices[d_amb[i]] = ix;
    }
}

// ---------------------------------------------------------------------------
// gather (+ usage histogram) + stats (2-phase, deterministic fixed trees)
// ---------------------------------------------------------------------------
__global__ void vq_gather_kernel(const float* __restrict__ ze,
                                 const float* __restrict__ emb,
                                 float* __restrict__ out) {
    int t = threadIdx.x;
    int m = blockIdx.x * 4 + (t >> 6);
    int l = t & 63;
    int idx = d_indices[m];
    float4 e = *(const float4*)(emb + (size_t)idx * DD + l * 4);
    float4 x = *(const float4*)(ze  + (size_t)m   * DD + l * 4);
    float4 st;
    st.x = x.x + (e.x - x.x); st.y = x.y + (e.y - x.y);
    st.z = x.z + (e.z - x.z); st.w = x.w + (e.w - x.w);
    *(float4*)(out + (size_t)m * DD + l * 4) = st;
    *(float4*)(out + (size_t)NN * DD + (size_t)m * DD + l * 4) = e;
    if (l == 0) {
        out[(size_t)2 * NN * DD + m] = (float)idx;
        atomicAdd(&d_usage[idx], 1);
    }
}

__global__ void vq_stats_part(void) {          // 8 blocks x 1024: one code/thread
    __shared__ float sH[32];
    __shared__ int   sD[32];
    int t = threadIdx.x;
    int k = blockIdx.x * 1024 + t;
    int u = d_usage[k];
    float H = 0.f; int dead = 0;
    if (u == 0) dead = 1;
    else { float p = (float)u * (1.0f / (float)NN); H = p * logf(p); }
#pragma unroll
    for (int o = 16; o; o >>= 1) {
        H    += __shfl_xor_sync(0xffffffffu, H, o);
        dead += __shfl_xor_sync(0xffffffffu, dead, o);
    }
    if ((t & 31) == 0) { sH[t >> 5] = H; sD[t >> 5] = dead; }
    __syncthreads();
    if (t == 0) {
        float Ht = 0.f; int dt = 0;
        for (int w = 0; w < 32; w++) { Ht += sH[w]; dt += sD[w]; }
        d_partH[blockIdx.x] = Ht;
        d_partD[blockIdx.x] = dt;
    }
}
__global__ void vq_stats_final(float* __restrict__ out) {
    if (threadIdx.x == 0) {
        float Ht = 0.f; int dt = 0;
        for (int b = 0; b < 8; b++) { Ht += d_partH[b]; dt += d_partD[b]; }
        size_t off = (size_t)2 * NN * DD + NN;
        out[off + 0] = expf(-Ht);
        out[off + 1] = (float)dt / (float)KK;
    }
}

// ---------------------------------------------------------------------------
extern "C" void kernel_launch(void* const* d_in, const int* in_sizes, int n_in,
                              void* d_out, int out_size) {
    const float* ze  = (const float*)d_in[0];
    const float* emb = (const float*)d_in[1];
    float* out = (float*)d_out;

    cudaFuncSetAttribute(vq_pass1_kernel, cudaFuncAttributeMaxDynamicSharedMemorySize,
                         P1_SMEM);
    cudaFuncSetAttribute(vq_rescue_kernel, cudaFuncAttributeMaxDynamicSharedMemorySize,
                         RS_SMEM);

    vq_split_ze<<<NN / 8, 256>>>(ze);
    vq_split_emb<<<KK / 8, 256>>>(emb);
    vq_pass1_kernel<<<NN / CTAM, 256, P1_SMEM>>>();
    vq_rescue_kernel<<<64 * NSPLIT, 256, RS_SMEM>>>();
    vq_amb_merge_kernel<<<NN / 256, 256>>>();
    vq_gather_kernel<<<NN / 4, 256>>>(ze, emb, out);
    vq_stats_part<<<8, 1024>>>();
    vq_stats_final<<<1, 32>>>(out);
}

// round 16
// speedup vs baseline: 1.1183x; 1.0727x over previous
#include <cuda_runtime.h>
#include <cuda_fp16.h>
#include <cstdint>

#define DD   256
#define KK   8192
#define NN   32768
#define CTAM 128
#define NSPLIT 16                 // rescue N-splits (512 codes each)

// ---- pass1 smem layout (A = a0 only, 4 planes; CTAN=128; 2-stage 16KB B ring)
#define P1_CTAN   128
#define P1_OFF_A  0               // 4 x 16384 = 65536
#define P1_OFF_B  65536           // 2 stages x 16384 = 32768
#define P1_OFF_HN 98304           // 128 floats
#define P1_SMEM   98816
#define P1_OFF_RV P1_OFF_B
#define P1_OFF_RI (P1_OFF_B + 2048)
#define P1_OFF_R2 (P1_OFF_B + 4096)

// ---- rescue smem layout (A = [a0|a1], 8 planes; 3-stage 32KB ring; CTAN=256)
#define CTAN 256
#define RS_OFF_A  0               // 8 x 16384 = 131072
#define RS_OFF_B  131072          // 3 stages x 32768
#define RS_OFF_HN 229376
#define RS_SMEM   230400
#define RS_OFF_RV RS_OFF_B
#define RS_OFF_RI (RS_OFF_B + 2048)

#define SWZ(x) ((x) ^ (((x) >> 3) & 0x70))

// Scratch (no allocations allowed)
__device__ float d_half_norm[KK];
__device__ float d_a0norm[NN];
__device__ float d_rxnorm[NN];
__device__ int   d_usage[KK];
__device__ int   d_indices[NN];
__device__ int   d_count;
__device__ int   d_b0max_bits;
__device__ int   d_remax_bits;
__device__ int   d_amb[NN];
__device__ unsigned long long d_best[NN];   // packed (ordered-score, idx) per amb row
__device__ float d_partH[8];
__device__ int   d_partD[8];
__device__ __half d_A[(size_t)NN * 512];   // [a0(256) | a1(256)] per row
__device__ __half d_B[(size_t)KK * 512];   // [b0(256) | b1(256)] per row

__device__ __forceinline__ uint32_t smem_u32(const void* p) {
    uint32_t a;
    asm("{ .reg .u64 t; cvta.to.shared.u64 t, %1; cvt.u32.u64 %0, t; }" : "=r"(a) : "l"(p));
    return a;
}
// monotone float -> uint32 (preserves total order, incl. negatives)
__device__ __forceinline__ uint32_t ford(float v) {
    uint32_t u = __float_as_uint(v);
    return (u & 0x80000000u) ? ~u : (u | 0x80000000u);
}

// ---------------------------------------------------------------------------
// Fused splits: exact 2-way fp16 split + exact split-part norms (warp per row)
// ---------------------------------------------------------------------------
__global__ void vq_split_ze(const float* __restrict__ src) {
    if (blockIdx.x == 0 && threadIdx.x == 0) {
        d_count = 0; d_b0max_bits = 0; d_remax_bits = 0;
    }
    int row  = blockIdx.x * 8 + (threadIdx.x >> 5);
    int lane = threadIdx.x & 31;
    const float4* x4 = (const float4*)(src + (size_t)row * DD + lane * 8);
    float4 v0 = x4[0], v1 = x4[1];
    float vv[8] = {v0.x, v0.y, v0.z, v0.w, v1.x, v1.y, v1.z, v1.w};
    __half h0[8], h1[8];
    float s0 = 0.f, s1 = 0.f;
#pragma unroll
    for (int i = 0; i < 8; ++i) {
        h0[i] = __float2half_rn(vv[i]);
        float f0 = __half2float(h0[i]);
        h1[i] = __float2half_rn(vv[i] - f0);
        float f1 = __half2float(h1[i]);
        s0 += f0 * f0;
        s1 += f1 * f1;
    }
#pragma unroll
    for (int o = 16; o; o >>= 1) {
        s0 += __shfl_xor_sync(0xffffffffu, s0, o);
        s1 += __shfl_xor_sync(0xffffffffu, s1, o);
    }
    if (lane == 0) { d_a0norm[row] = sqrtf(s0); d_rxnorm[row] = sqrtf(s1); }
    *(uint4*)(d_A + (size_t)row * 512 + lane * 8)       = *(uint4*)h0;
    *(uint4*)(d_A + (size_t)row * 512 + 256 + lane * 8) = *(uint4*)h1;
}
__global__ void vq_split_emb(const float* __restrict__ src) {
    int row  = blockIdx.x * 8 + (threadIdx.x >> 5);
    int lane = threadIdx.x & 31;
    const float4* x4 = (const float4*)(src + (size_t)row * DD + lane * 8);
    float4 v0 = x4[0], v1 = x4[1];
    float vv[8] = {v0.x, v0.y, v0.z, v0.w, v1.x, v1.y, v1.z, v1.w};
    __half h0[8], h1[8];
    float s = 0.f, s0 = 0.f, s1 = 0.f;
#pragma unroll
    for (int i = 0; i < 8; ++i) {
        h0[i] = __float2half_rn(vv[i]);
        float f0 = __half2float(h0[i]);
        h1[i] = __float2half_rn(vv[i] - f0);
        float f1 = __half2float(h1[i]);
        s  += vv[i] * vv[i];
        s0 += f0 * f0;
        s1 += f1 * f1;
    }
#pragma unroll
    for (int o = 16; o; o >>= 1) {
        s  += __shfl_xor_sync(0xffffffffu, s, o);
        s0 += __shfl_xor_sync(0xffffffffu, s0, o);
        s1 += __shfl_xor_sync(0xffffffffu, s1, o);
    }
    if (lane == 0) {
        d_half_norm[row] = 0.5f * s;
        atomicMax(&d_b0max_bits, __float_as_int(sqrtf(s0)));
        atomicMax(&d_remax_bits, __float_as_int(sqrtf(s1)));
    }
    *(uint4*)(d_B + (size_t)row * 512 + lane * 8)       = *(uint4*)h0;
    *(uint4*)(d_B + (size_t)row * 512 + 256 + lane * 8) = *(uint4*)h1;
    int g = blockIdx.x * blockDim.x + threadIdx.x;
    if (g < KK) d_usage[g] = 0;
}

// ---------------------------------------------------------------------------
// Pass 1: single-product (a0*b0) GEMM + min1/min2 + certification.
// CTAN=128, warp tile 64x32, occupancy 2.  Branchless min tracking.
// ---------------------------------------------------------------------------
__device__ __forceinline__ void p1_issue(uint32_t sb, int g2, int tid) {
    const int t2 = g2 >> 2, seg = g2 & 3;               // b0 segs 0-3
    const __half* src = d_B + (size_t)(t2 * P1_CTAN) * 512 + seg * 64;
    uint32_t db = sb + P1_OFF_B + (uint32_t)(g2 & 1) * 16384;
#pragma unroll
    for (int j = 0; j < 4; ++j) {
        int i = tid + 256 * j;                          // 0..1023 16B units
        int r = i >> 3, u = i & 7;
        const void* gp = (const void*)(src + (size_t)r * 512 + u * 8);
        uint32_t off = (uint32_t)(((r >> 3) << 10) + ((r & 7) << 7) + (u << 4));
        asm volatile("cp.async.cg.shared.global [%0], [%1], 16;"
                     :: "r"(db + SWZ(off)), "l"(gp));
    }
    asm volatile("cp.async.commit_group;" ::: "memory");
}

__global__ __launch_bounds__(256, 2) void vq_pass1_kernel() {
    extern __shared__ __align__(1024) char smem[];
    const uint32_t sb = smem_u32(smem);
    const int tid  = threadIdx.x;
    const int lane = tid & 31, wid = tid >> 5;
    const int wm = wid >> 2, wn = wid & 3;              // 2m x 4n warp grid
    const int m0 = blockIdx.x * CTAM;
    float* shn = (float*)(smem + P1_OFF_HN);

    // A resident: a0 only, 4 planes
    {
        const __half* Arow = d_A + (size_t)m0 * 512;
#pragma unroll
        for (int q = 0; q < 16; ++q) {
            int i = tid + 256 * q;            // 0..4095 16B units
            int p = i >> 10;
            int r = (i >> 3) & 127;
            int u = i & 7;
            uint4 v = *(const uint4*)(Arow + (size_t)r * 512 + p * 64 + u * 8);
            uint32_t off = (uint32_t)(p * 16384 + ((r >> 3) << 10) + ((r & 7) << 7) + (u << 4));
            *(uint4*)(smem + P1_OFF_A + SWZ(off)) = v;
        }
    }

    float acc[4][4][4];
#pragma unroll
    for (int mi = 0; mi < 4; ++mi)
#pragma unroll
        for (int ni = 0; ni < 4; ++ni)
#pragma unroll
            for (int k = 0; k < 4; ++k) acc[mi][ni][k] = 0.f;
    float m1[8], m2[8];
    int   i1[8];
#pragma unroll
    for (int i = 0; i < 8; ++i) { m1[i] = 3.4028235e38f; m2[i] = 3.4028235e38f; i1[i] = 0; }

    p1_issue(sb, 0, tid);

    const int NITER = (KK / P1_CTAN) * 4;               // 64 tiles x 4 chunks = 256
    for (int g = 0; g < NITER; ++g) {
        __syncthreads();
        if (g + 1 < NITER) {
            p1_issue(sb, g + 1, tid);
            asm volatile("cp.async.wait_group 1;" ::: "memory");
        } else {
            asm volatile("cp.async.wait_group 0;" ::: "memory");
        }
        __syncthreads();

        const int tile = g >> 2, c = g & 3;
        if (c == 0 && tid < 128) shn[tid] = d_half_norm[tile * P1_CTAN + tid];

        const uint32_t ab = sb + P1_OFF_A + (uint32_t)c * 16384;
        const uint32_t bb = sb + P1_OFF_B + (uint32_t)(g & 1) * 16384;
#pragma unroll
        for (int s = 0; s < 4; ++s) {
            uint32_t a[4][4];
#pragma unroll
            for (int mi = 0; mi < 4; ++mi) {
                int r = wm * 64 + mi * 16 + (lane & 7) + ((lane >> 3) & 1) * 8;
                int u = s * 2 + (lane >> 4);
                uint32_t off = ((uint32_t)(r >> 3) << 10) + ((uint32_t)(r & 7) << 7)
                             + ((uint32_t)u << 4);
                asm volatile("ldmatrix.sync.aligned.m8n8.x4.shared.b16 {%0,%1,%2,%3}, [%4];"
                    : "=r"(a[mi][0]), "=r"(a[mi][1]), "=r"(a[mi][2]), "=r"(a[mi][3])
                    : "r"(ab + SWZ(off)));
            }
            uint32_t b[4][2];
#pragma unroll
            for (int nq = 0; nq < 2; ++nq) {
                int r = wn * 32 + nq * 16 + (lane & 7) + ((lane >> 4) & 1) * 8;
                int u = s * 2 + ((lane >> 3) & 1);
                uint32_t off = ((uint32_t)(r >> 3) << 10) + ((uint32_t)(r & 7) << 7)
                             + ((uint32_t)u << 4);
                asm volatile("ldmatrix.sync.aligned.m8n8.x4.shared.b16 {%0,%1,%2,%3}, [%4];"
                    : "=r"(b[2*nq][0]), "=r"(b[2*nq][1]), "=r"(b[2*nq+1][0]), "=r"(b[2*nq+1][1])
                    : "r"(bb + SWZ(off)));
            }
#pragma unroll
            for (int mi = 0; mi < 4; ++mi)
#pragma unroll
                for (int ni = 0; ni < 4; ++ni)
                    asm volatile("mma.sync.aligned.m16n8k16.row.col.f32.f16.f16.f32 "
                        "{%0,%1,%2,%3}, {%4,%5,%6,%7}, {%8,%9}, {%0,%1,%2,%3};"
                        : "+f"(acc[mi][ni][0]), "+f"(acc[mi][ni][1]),
                          "+f"(acc[mi][ni][2]), "+f"(acc[mi][ni][3])
                        : "r"(a[mi][0]), "r"(a[mi][1]), "r"(a[mi][2]), "r"(a[mi][3]),
                          "r"(b[ni][0]), "r"(b[ni][1]));
        }

        if (c == 3) {
#pragma unroll
            for (int ni = 0; ni < 4; ++ni)
#pragma unroll
                for (int c2 = 0; c2 < 2; ++c2) {
                    int coll = wn * 32 + ni * 8 + (lane & 3) * 2 + c2;
                    float hv = shn[coll];
                    int gcol = tile * P1_CTAN + coll;
#pragma unroll
                    for (int mi = 0; mi < 4; ++mi)
#pragma unroll
                        for (int h = 0; h < 2; ++h) {
                            float sc = hv - acc[mi][ni][h * 2 + c2];
                            int rm = mi * 2 + h;
                            // branchless, exact-equivalent min1/min2 (inv: m1<=m2)
                            m2[rm] = fminf(m2[rm], fmaxf(sc, m1[rm]));
                            if (sc < m1[rm]) i1[rm] = gcol;
                            m1[rm] = fminf(m1[rm], sc);
                            acc[mi][ni][h * 2 + c2] = 0.f;
                        }
                }
        }
    }

    // reduce (m1,i1,m2) per row; scratch aliases B ring
    __syncthreads();
    float* rv = (float*)(smem + P1_OFF_RV);
    int*   ri = (int*)(smem + P1_OFF_RI);
    float* r2 = (float*)(smem + P1_OFF_R2);
#pragma unroll
    for (int rm = 0; rm < 8; ++rm) {
        float v = m1[rm], v2 = m2[rm];
        int ix = i1[rm];
#pragma unroll
        for (int o = 1; o <= 2; o <<= 1) {
            float ov  = __shfl_xor_sync(0xffffffffu, v, o);
            int   oi  = __shfl_xor_sync(0xffffffffu, ix, o);
            float ov2 = __shfl_xor_sync(0xffffffffu, v2, o);
            if (ov < v || (ov == v && oi < ix)) {
                v2 = fminf(v, ov2); v = ov; ix = oi;
            } else {
                v2 = fminf(v2, ov);
            }
        }
        if ((lane & 3) == 0) {
            int ml = wm * 64 + (rm >> 1) * 16 + (rm & 1) * 8 + (lane >> 2);
            rv[ml * 4 + wn] = v; ri[ml * 4 + wn] = ix; r2[ml * 4 + wn] = v2;
        }
    }
    __syncthreads();
    if (tid < 128) {
        float v = rv[tid * 4], v2 = r2[tid * 4];
        int ix = ri[tid * 4];
#pragma unroll
        for (int w = 1; w < 4; ++w) {
            float ov = rv[tid * 4 + w], ov2 = r2[tid * 4 + w];
            int oi = ri[tid * 4 + w];
            if (ov < v || (ov == v && oi < ix)) {
                v2 = fminf(v, ov2); v = ov; ix = oi;
            } else {
                v2 = fminf(v2, ov);
            }
        }
        const int row = m0 + tid;
        d_indices[row] = ix;
        // certified Cauchy-Schwarz bound with exact split-part norms:
        // |score_p1 - score_rescue| <= ||a0||*max||b1|| + ||a1||*max||b0||
        float thr = (d_a0norm[row] * __int_as_float(d_remax_bits)
                   + d_rxnorm[row] * __int_as_float(d_b0max_bits)) * 1.01f + 1e-4f;
        if (!(v2 - v > thr)) {
            int pos = atomicAdd(&d_count, 1);
            d_amb[pos] = row;
            d_best[row] = 0xFFFFFFFFFFFFFFFFull;
        }
    }
}

// ---------------------------------------------------------------------------
// Rescue: exact 3-product GEMM over ambiguous rows, N-split by 16 (512 codes).
// Grid 1024 blocks; each strides mt by 64. Result merged via packed atomicMin
// (order-preserved float || idx) -> deterministic min with lowest-idx ties.
// ---------------------------------------------------------------------------
__device__ __forceinline__ void rs_issue_b(uint32_t sb, int g2, int ns, int tid) {
    const int t2 = g2 / 12;
    const int c2 = g2 - t2 * 12;
    const int seg = (c2 < 8) ? c2 : (c2 - 8);
    const __half* src = d_B + (size_t)(ns * 512 + t2 * CTAN) * 512 + seg * 64;
    uint32_t db = sb + RS_OFF_B + (uint32_t)(g2 % 3) * 32768;
#pragma unroll
    for (int j = 0; j < 8; ++j) {
        int i = tid + 256 * j;
        int r = i >> 3, u = i & 7;
        const void* gp = (const void*)(src + (size_t)r * 512 + u * 8);
        uint32_t off = (uint32_t)(((r >> 3) << 10) + ((r & 7) << 7) + (u << 4));
        asm volatile("cp.async.cg.shared.global [%0], [%1], 16;"
                     :: "r"(db + SWZ(off)), "l"(gp));
    }
    asm volatile("cp.async.commit_group;" ::: "memory");
}

__global__ __launch_bounds__(256, 1) void vq_rescue_kernel() {
    const int count = d_count;
    const int ns  = blockIdx.x & 15;
    const int mt0 = blockIdx.x >> 4;                    // 0..63
    extern __shared__ __align__(1024) char smem[];
    const uint32_t sb = smem_u32(smem);
    const int tid  = threadIdx.x;
    const int lane = tid & 31, wid = tid >> 5;
    const int wm = wid >> 2, wn = wid & 3;
    float* shn = (float*)(smem + RS_OFF_HN);

    for (int mt = mt0; mt * CTAM < count; mt += 64) {
        const int m0 = mt * CTAM;
        __syncthreads();                                // smem reuse across mt iters

        // A resident: gather ambiguous rows, both planes
#pragma unroll
        for (int q = 0; q < 32; ++q) {
            int i = tid + 256 * q;            // 0..8191 16B units
            int p = i >> 10;
            int r = (i >> 3) & 127;
            int u = i & 7;
            int slot = m0 + r;
            int row = d_amb[slot < count ? slot : count - 1];
            uint4 v = *(const uint4*)(d_A + (size_t)row * 512 + p * 64 + u * 8);
            uint32_t off = (uint32_t)(p * 16384 + ((r >> 3) << 10) + ((r & 7) << 7) + (u << 4));
            *(uint4*)(smem + RS_OFF_A + SWZ(off)) = v;
        }

        float acc[4][8][4];
#pragma unroll
        for (int mi = 0; mi < 4; ++mi)
#pragma unroll
            for (int ni = 0; ni < 8; ++ni)
#pragma unroll
                for (int k = 0; k < 4; ++k) acc[mi][ni][k] = 0.f;
        float minv[8];
        int   mini[8];
#pragma unroll
        for (int i = 0; i < 8; ++i) { minv[i] = 3.4028235e38f; mini[i] = 0; }

        rs_issue_b(sb, 0, ns, tid);
        rs_issue_b(sb, 1, ns, tid);

        const int NITER = 2 * 12;                 // 2 tiles per split
        int tile = 0, c = 0;
        for (int g = 0; g < NITER; ++g) {
            if (g + 1 < NITER) {
                asm volatile("cp.async.wait_group 1;" ::: "memory");
            } else {
                asm volatile("cp.async.wait_group 0;" ::: "memory");
            }
            __syncthreads();
            if (g + 2 < NITER) rs_issue_b(sb, g + 2, ns, tid);

            if (c == 0) shn[tid] = d_half_norm[ns * 512 + tile * CTAN + tid];

            const int apl = (c < 8) ? (c & 3) : (c - 4);
            const uint32_t ab = sb + RS_OFF_A + (uint32_t)apl * 16384;
            const uint32_t bb = sb + RS_OFF_B + (uint32_t)(g % 3) * 32768;
#pragma unroll
            for (int s = 0; s < 4; ++s) {
                uint32_t a[4][4];
#pragma unroll
                for (int mi = 0; mi < 4; ++mi) {
                    int r = wm * 64 + mi * 16 + (lane & 7) + ((lane >> 3) & 1) * 8;
                    int u = s * 2 + (lane >> 4);
                    uint32_t off = ((uint32_t)(r >> 3) << 10) + ((uint32_t)(r & 7) << 7)
                                 + ((uint32_t)u << 4);
                    asm volatile("ldmatrix.sync.aligned.m8n8.x4.shared.b16 {%0,%1,%2,%3}, [%4];"
                        : "=r"(a[mi][0]), "=r"(a[mi][1]), "=r"(a[mi][2]), "=r"(a[mi][3])
                        : "r"(ab + SWZ(off)));
                }
                uint32_t b[8][2];
#pragma unroll
                for (int nq = 0; nq < 4; ++nq) {
                    int r = wn * 64 + nq * 16 + (lane & 7) + ((lane >> 4) & 1) * 8;
                    int u = s * 2 + ((lane >> 3) & 1);
                    uint32_t off = ((uint32_t)(r >> 3) << 10) + ((uint32_t)(r & 7) << 7)
                                 + ((uint32_t)u << 4);
                    asm volatile("ldmatrix.sync.aligned.m8n8.x4.shared.b16 {%0,%1,%2,%3}, [%4];"
                        : "=r"(b[2*nq][0]), "=r"(b[2*nq][1]), "=r"(b[2*nq+1][0]), "=r"(b[2*nq+1][1])
                        : "r"(bb + SWZ(off)));
                }
#pragma unroll
                for (int mi = 0; mi < 4; ++mi)
#pragma unroll
                    for (int ni = 0; ni < 8; ++ni)
                        asm volatile("mma.sync.aligned.m16n8k16.row.col.f32.f16.f16.f32 "
                            "{%0,%1,%2,%3}, {%4,%5,%6,%7}, {%8,%9}, {%0,%1,%2,%3};"
                            : "+f"(acc[mi][ni][0]), "+f"(acc[mi][ni][1]),
                              "+f"(acc[mi][ni][2]), "+f"(acc[mi][ni][3])
                            : "r"(a[mi][0]), "r"(a[mi][1]), "r"(a[mi][2]), "r"(a[mi][3]),
                              "r"(b[ni][0]), "r"(b[ni][1]));
            }

            if (c == 11) {
#pragma unroll
                for (int ni = 0; ni < 8; ++ni)
#pragma unroll
                    for (int c2 = 0; c2 < 2; ++c2) {
                        int coll = wn * 64 + ni * 8 + (lane & 3) * 2 + c2;
                        float hv = shn[coll];
                        int gcol = ns * 512 + tile * CTAN + coll;
#pragma unroll
                        for (int mi = 0; mi < 4; ++mi)
#pragma unroll
                            for (int h = 0; h < 2; ++h) {
                                float sc = hv - acc[mi][ni][h * 2 + c2];
                                int rm = mi * 2 + h;
                                if (sc < minv[rm]) mini[rm] = gcol;
                                minv[rm] = fminf(minv[rm], sc);
                                acc[mi][ni][h * 2 + c2] = 0.f;
                            }
                    }
                tile++; c = 0;
            } else {
                c++;
            }
        }

        __syncthreads();
        float* rv = (float*)(smem + RS_OFF_RV);
        int*   ri = (int*)(smem + RS_OFF_RI);
#pragma unroll
        for (int rm = 0; rm < 8; ++rm) {
            float v = minv[rm]; int ix = mini[rm];
#pragma unroll
            for (int o = 1; o <= 2; o <<= 1) {
                float ov = __shfl_xor_sync(0xffffffffu, v, o);
                int   oi = __shfl_xor_sync(0xffffffffu, ix, o);
                if (ov < v || (ov == v && oi < ix)) { v = ov; ix = oi; }
            }
            if ((lane & 3) == 0) {
                int ml = wm * 64 + (rm >> 1) * 16 + (rm & 1) * 8 + (lane >> 2);
                rv[ml * 4 + wn] = v;
                ri[ml * 4 + wn] = ix;
            }
        }
        __syncthreads();
        if (tid < 128) {
            float v = rv[tid * 4]; int ix = ri[tid * 4];
#pragma unroll
            for (int w = 1; w < 4; ++w) {
                float ov = rv[tid * 4 + w]; int oi = ri[tid * 4 + w];
                if (ov < v || (ov == v && oi < ix)) { v = ov; ix = oi; }
            }
            int slot = m0 + tid;
            if (slot < count) {
                unsigned long long key =
                    ((unsigned long long)ford(v) << 32) | (unsigned long long)(uint32_t)ix;
                atomicMin(&d_best[d_amb[slot]], key);
            }
        }
    }
}

__global__ void vq_amb_unpack_kernel() {
    int i = blockIdx.x * blockDim.x + threadIdx.x;
    if (i < d_count) {
        int row = d_amb[i];
        d_indices[row] = (int)(uint32_t)(d_best[row] & 0xFFFFFFFFull);
    }
}

// ---------------------------------------------------------------------------
// gather (+ usage histogram) + stats (2-phase, deterministic fixed trees)
// ---------------------------------------------------------------------------
__global__ void vq_gather_kernel(const float* __restrict__ ze,
                                 const float* __restrict__ emb,
                                 float* __restrict__ out) {
    int t = threadIdx.x;
    int m = blockIdx.x * 4 + (t >> 6);
    int l = t & 63;
    int idx = d_indices[m];
    float4 e = *(const float4*)(emb + (size_t)idx * DD + l * 4);
    float4 x = *(const float4*)(ze  + (size_t)m   * DD + l * 4);
    float4 st;
    st.x = x.x + (e.x - x.x); st.y = x.y + (e.y - x.y);
    st.z = x.z + (e.z - x.z); st.w = x.w + (e.w - x.w);
    *(float4*)(out + (size_t)m * DD + l * 4) = st;
    *(float4*)(out + (size_t)NN * DD + (size_t)m * DD + l * 4) = e;
    if (l == 0) {
        out[(size_t)2 * NN * DD + m] = (float)idx;
        atomicAdd(&d_usage[idx], 1);
    }
}

__global__ void vq_stats_part(void) {          // 8 blocks x 1024: one code/thread
    __shared__ float sH[32];
    __shared__ int   sD[32];
    int t = threadIdx.x;
    int k = blockIdx.x * 1024 + t;
    int u = d_usage[k];
    float H = 0.f; int dead = 0;
    if (u == 0) dead = 1;
    else { float p = (float)u * (1.0f / (float)NN); H = p * logf(p); }
#pragma unroll
    for (int o = 16; o; o >>= 1) {
        H    += __shfl_xor_sync(0xffffffffu, H, o);
        dead += __shfl_xor_sync(0xffffffffu, dead, o);
    }
    if ((t & 31) == 0) { sH[t >> 5] = H; sD[t >> 5] = dead; }
    __syncthreads();
    if (t == 0) {
        float Ht = 0.f; int dt = 0;
        for (int w = 0; w < 32; w++) { Ht += sH[w]; dt += sD[w]; }
        d_partH[blockIdx.x] = Ht;
        d_partD[blockIdx.x] = dt;
    }
}
__global__ void vq_stats_final(float* __restrict__ out) {
    if (threadIdx.x == 0) {
        float Ht = 0.f; int dt = 0;
        for (int b = 0; b < 8; b++) { Ht += d_partH[b]; dt += d_partD[b]; }
        size_t off = (size_t)2 * NN * DD + NN;
        out[off + 0] = expf(-Ht);
        out[off + 1] = (float)dt / (float)KK;
    }
}

// ---------------------------------------------------------------------------
extern "C" void kernel_launch(void* const* d_in, const int* in_sizes, int n_in,
                              void* d_out, int out_size) {
    const float* ze  = (const float*)d_in[0];
    const float* emb = (const float*)d_in[1];
    float* out = (float*)d_out;

    cudaFuncSetAttribute(vq_pass1_kernel, cudaFuncAttributeMaxDynamicSharedMemorySize,
                         P1_SMEM);
    cudaFuncSetAttribute(vq_rescue_kernel, cudaFuncAttributeMaxDynamicSharedMemorySize,
                         RS_SMEM);

    vq_split_ze<<<NN / 8, 256>>>(ze);
    vq_split_emb<<<KK / 8, 256>>>(emb);
    vq_pass1_kernel<<<NN / CTAM, 256, P1_SMEM>>>();
    vq_rescue_kernel<<<64 * NSPLIT, 256, RS_SMEM>>>();
    vq_amb_unpack_kernel<<<NN / 256, 256>>>();
    vq_gather_kernel<<<NN / 4, 256>>>(ze, emb, out);
    vq_stats_part<<<8, 1024>>>();
    vq_stats_final<<<1, 32>>>(out);
}